// round 1
// baseline (speedup 1.0000x reference)
#include <cuda_runtime.h>
#include <math.h>

#define B_     64
#define T_     127
#define S_     128
#define ENC_   2048
#define EMB_   512
#define HID_   512
#define VOCAB_ 10000
#define MS_    (B_*S_)          // 8192

// ---------------- static scratch (no cudaMalloc allowed) ----------------
__device__ float g_feat[B_*EMB_];            // fc1 raw output
__device__ float g_seq [B_*S_*EMB_];         // [b][s][d] LSTM input sequence
__device__ float g_xw  [B_*S_*4*HID_];       // precomputed x@w_ih^T + biases
__device__ float g_h   [2][B_*HID_];         // double-buffered hidden state
__device__ float g_c   [B_*HID_];            // cell state
__device__ float g_out [B_*S_*HID_];         // masked LSTM outputs
__device__ float g_sc  [B_*S_*S_];           // scores -> alpha (in place)
__device__ float g_attn[B_*S_*HID_];         // attention output

__device__ __forceinline__ float sigmoidf_(float x) { return 1.f / (1.f + expf(-x)); }

// ---------------- generic NT GEMM: C[m,n] = sum_k A[m,k]*B[n,k] (+bias) ----
// BM=BN=128, BK=8, 256 threads, 8x8 register tiles. Optional batching via z.
__global__ __launch_bounds__(256)
void sgemm_nt(const float* __restrict__ A, const float* __restrict__ Bm,
              const float* __restrict__ bias1, const float* __restrict__ bias2,
              float* __restrict__ C, int M, int N, int K,
              int sA, int sB, int sC)
{
    A  += (size_t)blockIdx.z * sA;
    Bm += (size_t)blockIdx.z * sB;
    C  += (size_t)blockIdx.z * sC;

    __shared__ float As[8][128];
    __shared__ float Bs[8][128];

    const int tid = threadIdx.x;
    const int bm  = blockIdx.y * 128;
    const int bn  = blockIdx.x * 128;
    const int lr  = tid >> 1;            // 0..127 loader row
    const int lc  = (tid & 1) * 4;       // 0 or 4  loader k-offset
    const int ty  = tid >> 4;            // 0..15
    const int tx  = tid & 15;            // 0..15

    float acc[8][8];
#pragma unroll
    for (int i = 0; i < 8; i++)
#pragma unroll
        for (int j = 0; j < 8; j++) acc[i][j] = 0.f;

    for (int k0 = 0; k0 < K; k0 += 8) {
        float4 a4 = make_float4(0.f, 0.f, 0.f, 0.f);
        float4 b4 = make_float4(0.f, 0.f, 0.f, 0.f);
        if (bm + lr < M) a4 = *(const float4*)&A [(size_t)(bm + lr) * K + k0 + lc];
        if (bn + lr < N) b4 = *(const float4*)&Bm[(size_t)(bn + lr) * K + k0 + lc];
        __syncthreads();
        As[lc + 0][lr] = a4.x; As[lc + 1][lr] = a4.y;
        As[lc + 2][lr] = a4.z; As[lc + 3][lr] = a4.w;
        Bs[lc + 0][lr] = b4.x; Bs[lc + 1][lr] = b4.y;
        Bs[lc + 2][lr] = b4.z; Bs[lc + 3][lr] = b4.w;
        __syncthreads();
#pragma unroll
        for (int k = 0; k < 8; k++) {
            float ar[8], br[8];
            *(float4*)&ar[0] = *(const float4*)&As[k][ty * 8];
            *(float4*)&ar[4] = *(const float4*)&As[k][ty * 8 + 4];
            *(float4*)&br[0] = *(const float4*)&Bs[k][tx * 8];
            *(float4*)&br[4] = *(const float4*)&Bs[k][tx * 8 + 4];
#pragma unroll
            for (int i = 0; i < 8; i++)
#pragma unroll
                for (int j = 0; j < 8; j++)
                    acc[i][j] += ar[i] * br[j];
        }
    }

#pragma unroll
    for (int i = 0; i < 8; i++) {
        int m = bm + ty * 8 + i;
        if (m >= M) continue;
#pragma unroll
        for (int j = 0; j < 8; j++) {
            int n = bn + tx * 8 + j;
            if (n < N) {
                float v = acc[i][j];
                if (bias1) v += bias1[n];
                if (bias2) v += bias2[n];
                C[(size_t)m * N + n] = v;
            }
        }
    }
}

// ---------------- batchnorm (batch stats) + write seq[:,0,:] -------------
__global__ void bn_k(const float* __restrict__ gamma, const float* __restrict__ beta)
{
    int j = blockIdx.x;          // feature column, 512 blocks
    int b = threadIdx.x;         // 64 threads
    float v = g_feat[b * EMB_ + j];
    __shared__ float s1[64], s2[64];
    s1[b] = v; s2[b] = v * v;
    __syncthreads();
    for (int off = 32; off > 0; off >>= 1) {
        if (b < off) { s1[b] += s1[b + off]; s2[b] += s2[b + off]; }
        __syncthreads();
    }
    float mu  = s1[0] * (1.f / 64.f);
    float var = s2[0] * (1.f / 64.f) - mu * mu;
    float r   = rsqrtf(var + 1e-5f);
    g_seq[(size_t)b * S_ * EMB_ + j] = (v - mu) * r * gamma[j] + beta[j];
}

// ---------------- embedding gather into seq[:,1:,:] ----------------------
__global__ void embed_k(const int* __restrict__ y, const float* __restrict__ emb)
{
    int i = blockIdx.x * blockDim.x + threadIdx.x;        // over B*T*128 float4
    if (i >= B_ * T_ * (EMB_ / 4)) return;
    int d4 = i & 127;
    int bt = i >> 7;
    int tt = bt % T_;
    int b  = bt / T_;
    int tok = y[b * T_ + tt];
    ((float4*)g_seq)[(size_t)(b * S_ + 1 + tt) * (EMB_ / 4) + d4] =
        ((const float4*)emb)[(size_t)tok * (EMB_ / 4) + d4];
}

// ---------------- zero h0 / c0 -------------------------------------------
__global__ void zero_k()
{
    int i = blockIdx.x * blockDim.x + threadIdx.x;
    if (i < B_ * HID_) { g_h[0][i] = 0.f; g_c[i] = 0.f; }
}

// ---------------- one LSTM time step (fused gemm + cell update) ----------
// grid 128 blocks x 128 threads. Block owns 4 h-columns (j0..j0+3), all 64 b,
// all 4 gates. Thread: (ks = k-half, jl = j-local, 4 batches). k-split 2.
__global__ __launch_bounds__(128)
void lstm_step(const float* __restrict__ w_hh, const int* __restrict__ lengths, int t)
{
    __shared__ float ws[4][4][512];     // [gate][j_local][k]  32KB
    __shared__ float red[64][16];       // k-split partials

    const float* h_in  = g_h[t & 1];
    float*       h_out = g_h[(t + 1) & 1];

    const int tid = threadIdx.x;
    const int j0  = blockIdx.x * 4;

    // stage weights: 4 gates x 4 cols x 512 k = 2048 float4
    for (int i = tid; i < 2048; i += 128) {
        int k4 = i & 127, j = (i >> 7) & 3, g = i >> 9;
        ((float4*)ws)[i] = *(const float4*)(w_hh + (size_t)(g * HID_ + j0 + j) * HID_ + k4 * 4);
    }
    __syncthreads();

    const int ks  = tid >> 6;           // 0/1 k-half
    const int sub = tid & 63;
    const int jl  = sub >> 4;           // 0..3
    const int b0  = (sub & 15) * 4;     // batch group of 4

    float acc[4][4];
#pragma unroll
    for (int bi = 0; bi < 4; bi++)
#pragma unroll
        for (int g = 0; g < 4; g++) acc[bi][g] = 0.f;

    if (ks == 0) {
#pragma unroll
        for (int bi = 0; bi < 4; bi++)
#pragma unroll
            for (int g = 0; g < 4; g++)
                acc[bi][g] = g_xw[((size_t)(b0 + bi) * S_ + t) * (4 * HID_) + g * HID_ + j0 + jl];
    }

    const int kbeg = ks * 256;
#pragma unroll 2
    for (int k = kbeg; k < kbeg + 256; k += 4) {
        float4 w4[4];
#pragma unroll
        for (int g = 0; g < 4; g++) w4[g] = *(const float4*)&ws[g][jl][k];
#pragma unroll
        for (int bi = 0; bi < 4; bi++) {
            float4 h4 = *(const float4*)&h_in[(b0 + bi) * HID_ + k];
#pragma unroll
            for (int g = 0; g < 4; g++)
                acc[bi][g] += h4.x * w4[g].x + h4.y * w4[g].y
                            + h4.z * w4[g].z + h4.w * w4[g].w;
        }
    }

    if (ks == 1) {
#pragma unroll
        for (int bi = 0; bi < 4; bi++)
#pragma unroll
            for (int g = 0; g < 4; g++)
                red[sub][bi * 4 + g] = acc[bi][g];
    }
    __syncthreads();

    if (ks == 0) {
        const int j = j0 + jl;
#pragma unroll
        for (int bi = 0; bi < 4; bi++) {
            int bb = b0 + bi;
            float vi = acc[bi][0] + red[sub][bi * 4 + 0];
            float vf = acc[bi][1] + red[sub][bi * 4 + 1];
            float vg = acc[bi][2] + red[sub][bi * 4 + 2];
            float vo = acc[bi][3] + red[sub][bi * 4 + 3];
            float gi = sigmoidf_(vi);
            float gf = sigmoidf_(vf);
            float gg = tanhf(vg);
            float go = sigmoidf_(vo);
            float c  = gf * g_c[bb * HID_ + j] + gi * gg;
            g_c[bb * HID_ + j] = c;
            float h = go * tanhf(c);
            h_out[bb * HID_ + j] = h;
            g_out[((size_t)bb * S_ + t) * HID_ + j] = (t < lengths[bb]) ? h : 0.f;
        }
    }
}

// ---------------- softmax with reference's zero-mask semantics -----------
// masked (s >= t) positions contribute value 0 to max and sum, alpha zeroed.
__global__ void softmax_mask()
{
    int w    = threadIdx.x >> 5;
    int lane = threadIdx.x & 31;
    int row  = blockIdx.x * 4 + w;        // 0..8191 = b*128 + t
    int t    = row & (S_ - 1);
    float* sc = g_sc + (size_t)row * S_;

    float v[4];
#pragma unroll
    for (int u = 0; u < 4; u++) {
        int s = lane + u * 32;
        float x = sc[s];
        v[u] = (s < t) ? x : 0.f;
    }
    float m = fmaxf(fmaxf(v[0], v[1]), fmaxf(v[2], v[3]));
#pragma unroll
    for (int off = 16; off > 0; off >>= 1)
        m = fmaxf(m, __shfl_xor_sync(0xffffffffu, m, off));
    float e[4], sum = 0.f;
#pragma unroll
    for (int u = 0; u < 4; u++) { e[u] = expf(v[u] - m); sum += e[u]; }
#pragma unroll
    for (int off = 16; off > 0; off >>= 1)
        sum += __shfl_xor_sync(0xffffffffu, sum, off);
    float inv = 1.f / sum;
#pragma unroll
    for (int u = 0; u < 4; u++) {
        int s = lane + u * 32;
        sc[s] = (s < t) ? e[u] * inv : 0.f;
    }
}

// ---------------- attn[t,d] = sum_s alpha[t,s] * out[s,d] ----------------
__global__ __launch_bounds__(256)
void attn_mm()
{
    int b  = blockIdx.y;
    int t0 = blockIdx.x * 16;
    __shared__ float al[16][128];
    int tid = threadIdx.x;
    for (int i = tid; i < 16 * 128; i += 256)
        al[i >> 7][i & 127] = g_sc[((size_t)b * S_ + t0 + (i >> 7)) * S_ + (i & 127)];
    __syncthreads();

    int d0 = tid * 2;
    float2 acc[16];
#pragma unroll
    for (int t = 0; t < 16; t++) acc[t] = make_float2(0.f, 0.f);

    for (int s = 0; s < 128; s++) {
        float2 o = *(const float2*)&g_out[((size_t)b * S_ + s) * HID_ + d0];
#pragma unroll
        for (int t = 0; t < 16; t++) {
            float a = al[t][s];
            acc[t].x += a * o.x;
            acc[t].y += a * o.y;
        }
    }
#pragma unroll
    for (int t = 0; t < 16; t++)
        *(float2*)&g_attn[((size_t)b * S_ + t0 + t) * HID_ + d0] = acc[t];
}

// ---------------- launch -------------------------------------------------
extern "C" void kernel_launch(void* const* d_in, const int* in_sizes, int n_in,
                              void* d_out, int out_size)
{
    const float* x      = (const float*)d_in[0];
    const int*   y      = (const int*)  d_in[1];
    const int*   len    = (const int*)  d_in[2];
    const float* fc1_w  = (const float*)d_in[3];
    const float* fc1_b  = (const float*)d_in[4];
    const float* bn_g   = (const float*)d_in[5];
    const float* bn_b   = (const float*)d_in[6];
    const float* emb    = (const float*)d_in[7];
    const float* w_ih   = (const float*)d_in[8];
    const float* w_hh   = (const float*)d_in[9];
    const float* b_ih   = (const float*)d_in[10];
    const float* b_hh   = (const float*)d_in[11];
    const float* fc2_w  = (const float*)d_in[12];
    const float* fc2_b  = (const float*)d_in[13];
    float* out = (float*)d_out;

    float *p_feat, *p_seq, *p_xw, *p_out, *p_sc, *p_attn;
    cudaGetSymbolAddress((void**)&p_feat, g_feat);
    cudaGetSymbolAddress((void**)&p_seq,  g_seq);
    cudaGetSymbolAddress((void**)&p_xw,   g_xw);
    cudaGetSymbolAddress((void**)&p_out,  g_out);
    cudaGetSymbolAddress((void**)&p_sc,   g_sc);
    cudaGetSymbolAddress((void**)&p_attn, g_attn);

    // fc1: feat_raw = x @ fc1_w^T + fc1_b       [64, 512]
    sgemm_nt<<<dim3(4, 1, 1), 256>>>(x, fc1_w, fc1_b, nullptr, p_feat,
                                     B_, EMB_, ENC_, 0, 0, 0);
    // batchnorm -> seq[:,0,:]
    bn_k<<<EMB_, 64>>>(bn_g, bn_b);
    // embedding gather -> seq[:,1:,:]
    embed_k<<<(B_ * T_ * (EMB_ / 4) + 255) / 256, 256>>>(y, emb);
    // xW = seq @ w_ih^T + b_ih + b_hh          [8192, 2048]
    sgemm_nt<<<dim3(16, 64, 1), 256>>>(p_seq, w_ih, b_ih, b_hh, p_xw,
                                       MS_, 4 * HID_, EMB_, 0, 0, 0);
    // init recurrent state
    zero_k<<<128, 256>>>();
    // sequential LSTM
    for (int t = 0; t < S_; t++)
        lstm_step<<<128, 128>>>(w_hh, len, t);
    // scores[b] = out_b @ out_b^T  (batched NT gemm, one block per batch)
    sgemm_nt<<<dim3(1, 1, B_), 256>>>(p_out, p_out, nullptr, nullptr, p_sc,
                                      S_, S_, HID_, S_ * HID_, S_ * HID_, S_ * S_);
    // masked softmax (reference's zero-fill semantics), alpha in place
    softmax_mask<<<MS_ / 4, 128>>>();
    // attn = (alpha * cmask) @ out
    attn_mm<<<dim3(8, B_), 256>>>();
    // predictions = attn @ fc2_w^T + fc2_b     [8192, 10000]
    sgemm_nt<<<dim3(79, 64, 1), 256>>>(p_attn, fc2_w, fc2_b, nullptr, out,
                                       MS_, VOCAB_, HID_, 0, 0, 0);
}

// round 4
// speedup vs baseline: 1.4378x; 1.4378x over previous
#include <cuda_runtime.h>
#include <math.h>

#define B_     64
#define T_     127
#define S_     128
#define ENC_   2048
#define EMB_   512
#define HID_   512
#define VOCAB_ 10000
#define MS_    (B_*S_)          // 8192

// ---------------- static scratch (no cudaMalloc allowed) ----------------
__device__ float g_fc1p[8*B_*EMB_];          // fc1 split-K partials
__device__ float g_feat[B_*EMB_];            // fc1 raw output
__device__ float g_seq [B_*S_*EMB_];         // [b][s][d] LSTM input sequence
__device__ float g_xw  [B_*S_*4*HID_];       // precomputed x@w_ih^T + biases
__device__ float g_h   [2][B_*HID_];         // double-buffered hidden state
__device__ float g_c   [B_*HID_];            // cell state
__device__ float g_out [B_*S_*HID_];         // masked LSTM outputs
__device__ float g_sc  [B_*S_*S_];           // scores -> alpha (in place)
__device__ float g_attn[B_*S_*HID_];         // attention output
__device__ unsigned g_bar;                   // global step barrier counter

__device__ __forceinline__ float sigmoidf_(float x) { return 1.f / (1.f + expf(-x)); }

// ---------------- generic NT GEMM: C[m,n] = sum_k A[m,k]*B[n,k] (+bias) ----
__global__ __launch_bounds__(256)
void sgemm_nt(const float* __restrict__ A, const float* __restrict__ Bm,
              const float* __restrict__ bias1, const float* __restrict__ bias2,
              float* __restrict__ C, int M, int N, int K,
              int sA, int sB, int sC)
{
    A  += (size_t)blockIdx.z * sA;
    Bm += (size_t)blockIdx.z * sB;
    C  += (size_t)blockIdx.z * sC;

    __shared__ float As[8][128];
    __shared__ float Bs[8][128];

    const int tid = threadIdx.x;
    const int bm  = blockIdx.y * 128;
    const int bn  = blockIdx.x * 128;
    const int lr  = tid >> 1;
    const int lc  = (tid & 1) * 4;
    const int ty  = tid >> 4;
    const int tx  = tid & 15;

    float acc[8][8];
#pragma unroll
    for (int i = 0; i < 8; i++)
#pragma unroll
        for (int j = 0; j < 8; j++) acc[i][j] = 0.f;

    for (int k0 = 0; k0 < K; k0 += 8) {
        float4 a4 = make_float4(0.f, 0.f, 0.f, 0.f);
        float4 b4 = make_float4(0.f, 0.f, 0.f, 0.f);
        if (bm + lr < M) a4 = *(const float4*)&A [(size_t)(bm + lr) * K + k0 + lc];
        if (bn + lr < N) b4 = *(const float4*)&Bm[(size_t)(bn + lr) * K + k0 + lc];
        __syncthreads();
        As[lc + 0][lr] = a4.x; As[lc + 1][lr] = a4.y;
        As[lc + 2][lr] = a4.z; As[lc + 3][lr] = a4.w;
        Bs[lc + 0][lr] = b4.x; Bs[lc + 1][lr] = b4.y;
        Bs[lc + 2][lr] = b4.z; Bs[lc + 3][lr] = b4.w;
        __syncthreads();
#pragma unroll
        for (int k = 0; k < 8; k++) {
            float ar[8], br[8];
            *(float4*)&ar[0] = *(const float4*)&As[k][ty * 8];
            *(float4*)&ar[4] = *(const float4*)&As[k][ty * 8 + 4];
            *(float4*)&br[0] = *(const float4*)&Bs[k][tx * 8];
            *(float4*)&br[4] = *(const float4*)&Bs[k][tx * 8 + 4];
#pragma unroll
            for (int i = 0; i < 8; i++)
#pragma unroll
                for (int j = 0; j < 8; j++)
                    acc[i][j] += ar[i] * br[j];
        }
    }

#pragma unroll
    for (int i = 0; i < 8; i++) {
        int m = bm + ty * 8 + i;
        if (m >= M) continue;
#pragma unroll
        for (int j = 0; j < 8; j++) {
            int n = bn + tx * 8 + j;
            if (n < N) {
                float v = acc[i][j];
                if (bias1) v += bias1[n];
                if (bias2) v += bias2[n];
                C[(size_t)m * N + n] = v;
            }
        }
    }
}

// ---------------- fc1 split-K: partials over 8 k-chunks -------------------
__global__ __launch_bounds__(256)
void fc1_part(const float* __restrict__ x, const float* __restrict__ w)
{
    const int nt = blockIdx.x, kt = blockIdx.y;
    __shared__ float xs[64][68];     // stride 272B = 16B multiple
    __shared__ float ws[64][68];
    const int tid = threadIdx.x;
    const int ty = tid >> 4, tx = tid & 15;

    float acc[4][4];
#pragma unroll
    for (int i = 0; i < 4; i++)
#pragma unroll
        for (int j = 0; j < 4; j++) acc[i][j] = 0.f;

    for (int kc = 0; kc < 4; kc++) {
        int k0 = kt * 256 + kc * 64;
        for (int i = tid; i < 64 * 16; i += 256) {
            int r = i >> 4, c4 = (i & 15) * 4;
            *(float4*)&xs[r][c4] = *(const float4*)&x[(size_t)r * ENC_ + k0 + c4];
            *(float4*)&ws[r][c4] = *(const float4*)&w[(size_t)(nt * 64 + r) * ENC_ + k0 + c4];
        }
        __syncthreads();
#pragma unroll 8
        for (int k = 0; k < 64; k++) {
            float a[4], b[4];
#pragma unroll
            for (int i = 0; i < 4; i++) a[i] = xs[ty * 4 + i][k];
#pragma unroll
            for (int j = 0; j < 4; j++) b[j] = ws[tx * 4 + j][k];
#pragma unroll
            for (int i = 0; i < 4; i++)
#pragma unroll
                for (int j = 0; j < 4; j++) acc[i][j] += a[i] * b[j];
        }
        __syncthreads();
    }
#pragma unroll
    for (int i = 0; i < 4; i++)
#pragma unroll
        for (int j = 0; j < 4; j++)
            g_fc1p[((size_t)kt * B_ + ty * 4 + i) * EMB_ + nt * 64 + tx * 4 + j] = acc[i][j];
}

__global__ void fc1_reduce(const float* __restrict__ b1)
{
    int b = blockIdx.x, j = threadIdx.x;    // grid 64, 512 threads
    float s = b1[j];
#pragma unroll
    for (int kt = 0; kt < 8; kt++) s += g_fc1p[((size_t)kt * B_ + b) * EMB_ + j];
    g_feat[b * EMB_ + j] = s;
}

// ---------------- batchnorm (batch stats) + write seq[:,0,:] -------------
__global__ void bn_k(const float* __restrict__ gamma, const float* __restrict__ beta)
{
    int j = blockIdx.x;
    int b = threadIdx.x;
    float v = g_feat[b * EMB_ + j];
    __shared__ float s1[64], s2[64];
    s1[b] = v; s2[b] = v * v;
    __syncthreads();
    for (int off = 32; off > 0; off >>= 1) {
        if (b < off) { s1[b] += s1[b + off]; s2[b] += s2[b + off]; }
        __syncthreads();
    }
    float mu  = s1[0] * (1.f / 64.f);
    float var = s2[0] * (1.f / 64.f) - mu * mu;
    float r   = rsqrtf(var + 1e-5f);
    g_seq[(size_t)b * S_ * EMB_ + j] = (v - mu) * r * gamma[j] + beta[j];
}

// ---------------- embedding gather into seq[:,1:,:] ----------------------
__global__ void embed_k(const int* __restrict__ y, const float* __restrict__ emb)
{
    int i = blockIdx.x * blockDim.x + threadIdx.x;
    if (i >= B_ * T_ * (EMB_ / 4)) return;
    int d4 = i & 127;
    int bt = i >> 7;
    int tt = bt % T_;
    int b  = bt / T_;
    int tok = y[b * T_ + tt];
    ((float4*)g_seq)[(size_t)(b * S_ + 1 + tt) * (EMB_ / 4) + d4] =
        ((const float4*)emb)[(size_t)tok * (EMB_ / 4) + d4];
}

// ---------------- zero h0 / c0 / barrier ---------------------------------
__global__ void zero_k()
{
    int i = blockIdx.x * blockDim.x + threadIdx.x;
    if (i < B_ * HID_) { g_h[0][i] = 0.f; g_c[i] = 0.f; }
    if (i == 0) g_bar = 0u;
}

// ---------------- persistent LSTM: all 128 steps in one kernel -----------
// 128 blocks x 256 threads, 1 block/SM (big smem). Block owns 4 h-columns
// (all 4 gates). Weights staged to smem ONCE. Device-wide spin barrier per step.
#define WS_STRIDE 516
__global__ __launch_bounds__(256)
void lstm_all(const float* __restrict__ w_hh, const int* __restrict__ lengths)
{
    extern __shared__ float sm[];
    float* ws  = sm;                       // 16 * 516
    float* hs  = ws + 16 * WS_STRIDE;      // 64 * 516
    float* red = hs + 64 * WS_STRIDE;      // 3 * 64 * 16

    const int tid = threadIdx.x;
    const int j0  = blockIdx.x * 4;

    // stage weights once: rows r = g*4+jl  <- w_hh[g*512 + j0+jl][:]
    for (int i = tid; i < 16 * 128; i += 256) {
        int k4 = i & 127, r = i >> 7;
        int g = r >> 2, jl = r & 3;
        *(float4*)&ws[r * WS_STRIDE + k4 * 4] =
            *(const float4*)(w_hh + (size_t)(g * HID_ + j0 + jl) * HID_ + k4 * 4);
    }

    const int ks  = tid >> 6;           // 0..3 k-quarter
    const int sub = tid & 63;
    const int jl  = sub >> 4;           // 0..3
    const int b0  = (sub & 15) * 4;     // batch group of 4
    const int j   = j0 + jl;

    volatile unsigned* vbar = &g_bar;

    float creg[4];
    if (ks == 0) {
#pragma unroll
        for (int bi = 0; bi < 4; bi++) creg[bi] = 0.f;
    }

    __syncthreads();   // ws ready

    for (int t = 0; t < S_; t++) {
        // wait for all blocks to have finished step t-1
        if (tid == 0) {
            unsigned target = 128u * (unsigned)t;
            while (*vbar < target) { }
        }
        __syncthreads();

        // stage FULL h_in into smem (bypass L1: other SMs wrote it).
        // 64 batches * 128 float4 = 8192 float4, 32 per thread, coalesced.
        const float4* h_in4 = (const float4*)g_h[t & 1];
#pragma unroll 8
        for (int i = tid; i < 64 * 128; i += 256) {
            int b  = i >> 7;
            int k4 = i & 127;
            float4 v = __ldcv(&h_in4[i]);
            *(float4*)&hs[b * WS_STRIDE + k4 * 4] = v;
        }
        __syncthreads();

        float acc[4][4];
        if (ks == 0) {
#pragma unroll
            for (int bi = 0; bi < 4; bi++)
#pragma unroll
                for (int g = 0; g < 4; g++)
                    acc[bi][g] = g_xw[((size_t)(b0 + bi) * S_ + t) * (4 * HID_) + g * HID_ + j];
        } else {
#pragma unroll
            for (int bi = 0; bi < 4; bi++)
#pragma unroll
                for (int g = 0; g < 4; g++) acc[bi][g] = 0.f;
        }

        const int kbeg = ks * 128;
#pragma unroll 4
        for (int k = kbeg; k < kbeg + 128; k += 4) {
            float4 w4[4];
#pragma unroll
            for (int g = 0; g < 4; g++)
                w4[g] = *(const float4*)&ws[(g * 4 + jl) * WS_STRIDE + k];
#pragma unroll
            for (int bi = 0; bi < 4; bi++) {
                float4 h4 = *(const float4*)&hs[(b0 + bi) * WS_STRIDE + k];
#pragma unroll
                for (int g = 0; g < 4; g++)
                    acc[bi][g] += h4.x * w4[g].x + h4.y * w4[g].y
                                + h4.z * w4[g].z + h4.w * w4[g].w;
            }
        }

        if (ks > 0) {
#pragma unroll
            for (int bi = 0; bi < 4; bi++)
#pragma unroll
                for (int g = 0; g < 4; g++)
                    red[(((ks - 1) * 64 + sub) * 16) + bi * 4 + g] = acc[bi][g];
        }
        __syncthreads();

        if (ks == 0) {
            float* h_out = g_h[(t + 1) & 1];
#pragma unroll
            for (int bi = 0; bi < 4; bi++) {
                int bb = b0 + bi;
                float vi = acc[bi][0], vf = acc[bi][1], vg = acc[bi][2], vo = acc[bi][3];
#pragma unroll
                for (int r = 0; r < 3; r++) {
                    vi += red[((r * 64 + sub) * 16) + bi * 4 + 0];
                    vf += red[((r * 64 + sub) * 16) + bi * 4 + 1];
                    vg += red[((r * 64 + sub) * 16) + bi * 4 + 2];
                    vo += red[((r * 64 + sub) * 16) + bi * 4 + 3];
                }
                float gi = sigmoidf_(vi);
                float gf = sigmoidf_(vf);
                float gg = tanhf(vg);
                float go = sigmoidf_(vo);
                float c  = gf * creg[bi] + gi * gg;
                creg[bi] = c;
                float h = go * tanhf(c);
                h_out[bb * HID_ + j] = h;
                g_out[((size_t)bb * S_ + t) * HID_ + j] = (t < lengths[bb]) ? h : 0.f;
            }
            __threadfence();
        }
        __syncthreads();
        if (tid == 0) atomicAdd(&g_bar, 1u);
    }
}

// ---------------- softmax with reference's zero-mask semantics -----------
__global__ void softmax_mask()
{
    int w    = threadIdx.x >> 5;
    int lane = threadIdx.x & 31;
    int row  = blockIdx.x * 4 + w;
    int t    = row & (S_ - 1);
    float* sc = g_sc + (size_t)row * S_;

    float v[4];
#pragma unroll
    for (int u = 0; u < 4; u++) {
        int s = lane + u * 32;
        float x = sc[s];
        v[u] = (s < t) ? x : 0.f;
    }
    float m = fmaxf(fmaxf(v[0], v[1]), fmaxf(v[2], v[3]));
#pragma unroll
    for (int off = 16; off > 0; off >>= 1)
        m = fmaxf(m, __shfl_xor_sync(0xffffffffu, m, off));
    float e[4], sum = 0.f;
#pragma unroll
    for (int u = 0; u < 4; u++) { e[u] = expf(v[u] - m); sum += e[u]; }
#pragma unroll
    for (int off = 16; off > 0; off >>= 1)
        sum += __shfl_xor_sync(0xffffffffu, sum, off);
    float inv = 1.f / sum;
#pragma unroll
    for (int u = 0; u < 4; u++) {
        int s = lane + u * 32;
        sc[s] = (s < t) ? e[u] * inv : 0.f;
    }
}

// ---------------- attn[t,d] = sum_s alpha[t,s] * out[s,d] ----------------
__global__ __launch_bounds__(256)
void attn_mm()
{
    int b  = blockIdx.y;
    int t0 = blockIdx.x * 16;
    __shared__ float al[16][128];
    int tid = threadIdx.x;
    for (int i = tid; i < 16 * 128; i += 256)
        al[i >> 7][i & 127] = g_sc[((size_t)b * S_ + t0 + (i >> 7)) * S_ + (i & 127)];
    __syncthreads();

    int d0 = tid * 2;
    float2 acc[16];
#pragma unroll
    for (int t = 0; t < 16; t++) acc[t] = make_float2(0.f, 0.f);

    for (int s = 0; s < 128; s++) {
        float2 o = *(const float2*)&g_out[((size_t)b * S_ + s) * HID_ + d0];
#pragma unroll
        for (int t = 0; t < 16; t++) {
            float a = al[t][s];
            acc[t].x += a * o.x;
            acc[t].y += a * o.y;
        }
    }
#pragma unroll
    for (int t = 0; t < 16; t++)
        *(float2*)&g_attn[((size_t)b * S_ + t0 + t) * HID_ + d0] = acc[t];
}

// ---------------- launch -------------------------------------------------
extern "C" void kernel_launch(void* const* d_in, const int* in_sizes, int n_in,
                              void* d_out, int out_size)
{
    const float* x      = (const float*)d_in[0];
    const int*   y      = (const int*)  d_in[1];
    const int*   len    = (const int*)  d_in[2];
    const float* fc1_w  = (const float*)d_in[3];
    const float* fc1_b  = (const float*)d_in[4];
    const float* bn_g   = (const float*)d_in[5];
    const float* bn_b   = (const float*)d_in[6];
    const float* emb    = (const float*)d_in[7];
    const float* w_ih   = (const float*)d_in[8];
    const float* w_hh   = (const float*)d_in[9];
    const float* b_ih   = (const float*)d_in[10];
    const float* b_hh   = (const float*)d_in[11];
    const float* fc2_w  = (const float*)d_in[12];
    const float* fc2_b  = (const float*)d_in[13];
    float* out = (float*)d_out;

    float *p_seq, *p_xw, *p_out, *p_sc, *p_attn;
    cudaGetSymbolAddress((void**)&p_seq,  g_seq);
    cudaGetSymbolAddress((void**)&p_xw,   g_xw);
    cudaGetSymbolAddress((void**)&p_out,  g_out);
    cudaGetSymbolAddress((void**)&p_sc,   g_sc);
    cudaGetSymbolAddress((void**)&p_attn, g_attn);

    const int LSTM_SMEM = (16 * WS_STRIDE + 64 * WS_STRIDE + 3 * 64 * 16) * 4;
    cudaFuncSetAttribute(lstm_all, cudaFuncAttributeMaxDynamicSharedMemorySize, LSTM_SMEM);

    // fc1 split-K: partials + reduce
    fc1_part<<<dim3(8, 8), 256>>>(x, fc1_w);
    fc1_reduce<<<64, 512>>>(fc1_b);
    // batchnorm -> seq[:,0,:]
    bn_k<<<EMB_, 64>>>(bn_g, bn_b);
    // embedding gather -> seq[:,1:,:]
    embed_k<<<(B_ * T_ * (EMB_ / 4) + 255) / 256, 256>>>(y, emb);
    // xW = seq @ w_ih^T + b_ih + b_hh          [8192, 2048]
    sgemm_nt<<<dim3(16, 64, 1), 256>>>(p_seq, w_ih, b_ih, b_hh, p_xw,
                                       MS_, 4 * HID_, EMB_, 0, 0, 0);
    // init recurrent state + barrier
    zero_k<<<128, 256>>>();
    // persistent LSTM (all 128 steps)
    lstm_all<<<128, 256, LSTM_SMEM>>>(w_hh, len);
    // scores[b] = out_b @ out_b^T
    sgemm_nt<<<dim3(1, 1, B_), 256>>>(p_out, p_out, nullptr, nullptr, p_sc,
                                      S_, S_, HID_, S_ * HID_, S_ * HID_, S_ * S_);
    // masked softmax
    softmax_mask<<<MS_ / 4, 128>>>();
    // attn = (alpha * cmask) @ out
    attn_mm<<<dim3(8, B_), 256>>>();
    // predictions = attn @ fc2_w^T + fc2_b     [8192, 10000]
    sgemm_nt<<<dim3(79, 64, 1), 256>>>(p_attn, fc2_w, fc2_b, nullptr, out,
                                       MS_, VOCAB_, HID_, 0, 0, 0);
}

// round 6
// speedup vs baseline: 2.0537x; 1.4283x over previous
#include <cuda_runtime.h>
#include <cuda_bf16.h>
#include <math.h>
#include <stdint.h>

#define B_     64
#define T_     127
#define S_     128
#define ENC_   2048
#define EMB_   512
#define HID_   512
#define VOCAB_ 10000
#define MS_    (B_*S_)          // 8192
#define VPAD_  10112            // 79*128
#define KSPL_  1536             // 3*512 split-K' for bf16 3-term GEMM

// ---------------- static scratch (no cudaMalloc allowed) ----------------
__device__ float g_fc1p[8*B_*EMB_];
__device__ float g_feat[B_*EMB_];
__device__ float g_seq [B_*S_*EMB_];
__device__ float g_xw  [B_*S_*4*HID_];
__device__ float g_h   [2][B_*HID_];
__device__ float g_c   [B_*HID_];
__device__ float g_out [B_*S_*HID_];
__device__ float g_sc  [B_*S_*S_];
__device__ float g_attn[B_*S_*HID_];
__device__ unsigned g_bar;
__device__ __nv_bfloat16 g_abf  [MS_  * KSPL_];   // attn split  [Ah|Ah|Al]
__device__ __nv_bfloat16 g_wbf  [VPAD_* KSPL_];   // fc2_w split [Bh|Bl|Bh]
__device__ __nv_bfloat16 g_sbf  [MS_  * KSPL_];   // seq split
__device__ __nv_bfloat16 g_wihbf[2048 * KSPL_];   // w_ih split

__device__ __forceinline__ float sigmoidf_(float x) { return 1.f / (1.f + expf(-x)); }

__device__ __forceinline__ uint32_t smem_u32(const void* p) {
    uint32_t a;
    asm("{ .reg .u64 t; cvta.to.shared.u64 t, %1; cvt.u32.u64 %0, t; }" : "=r"(a) : "l"(p));
    return a;
}
#define CP_ASYNC16(dst, src) asm volatile("cp.async.cg.shared.global [%0], [%1], 16;" :: "r"(dst), "l"(src) : "memory")
#define CP_COMMIT()          asm volatile("cp.async.commit_group;" ::: "memory")
#define CP_WAIT1()           asm volatile("cp.async.wait_group 1;" ::: "memory")
#define CP_WAIT0()           asm volatile("cp.async.wait_group 0;" ::: "memory")

// ============ bf16 warp-MMA NT GEMM: C[m,n] = sum A'[m,k]B'[n,k] + bias ===
// BM=BN=128, BK=32, K'=1536 (48 chunks). 256 threads = 8 warps, warp tile
// 32x64 (mma m16n8k16: 2 M-tiles x 8 N-tiles). Double-buffered cp.async,
// XOR swizzle key=(row>>1)&3 on 16B chunks (4/row).
__global__ __launch_bounds__(256)
void bf16_gemm_mma(const __nv_bfloat16* __restrict__ A,
                   const __nv_bfloat16* __restrict__ Bm,
                   const float* __restrict__ bias1,
                   const float* __restrict__ bias2,
                   float* __restrict__ C, int Nreal, int ldc)
{
    __shared__ __align__(16) __nv_bfloat16 sA[2][128 * 32];
    __shared__ __align__(16) __nv_bfloat16 sB[2][128 * 32];

    const int tid  = threadIdx.x;
    const int warp = tid >> 5;
    const int lane = tid & 31;
    const int wm0  = (warp & 3) * 32;     // warp M offset
    const int wn0  = (warp >> 2) * 64;    // warp N offset
    const int bm   = blockIdx.y * 128;
    const int bn   = blockIdx.x * 128;

    const uint32_t aBase[2] = { smem_u32(&sA[0][0]), smem_u32(&sA[1][0]) };
    const uint32_t bBase[2] = { smem_u32(&sB[0][0]), smem_u32(&sB[1][0]) };

    float acc[2][8][4];
#pragma unroll
    for (int mt = 0; mt < 2; mt++)
#pragma unroll
        for (int nt = 0; nt < 8; nt++)
#pragma unroll
            for (int u = 0; u < 4; u++) acc[mt][nt][u] = 0.f;

    // loader: idx = tid*2 + {0,1} over 512 chunks: row = idx>>2, chunk = idx&3
    const int idx0 = tid * 2;

#define LOAD_TILE(buf, c)                                                        \
    {                                                                            \
        _Pragma("unroll")                                                        \
        for (int u = 0; u < 2; u++) {                                            \
            int idx = idx0 + u;                                                  \
            int r = idx >> 2, ch = idx & 3;                                      \
            int ph = ch ^ ((r >> 1) & 3);                                        \
            CP_ASYNC16(aBase[buf] + (r * 4 + ph) * 16,                           \
                       A + (size_t)(bm + r) * KSPL_ + (c) * 32 + ch * 8);        \
            CP_ASYNC16(bBase[buf] + (r * 4 + ph) * 16,                           \
                       Bm + (size_t)(bn + r) * KSPL_ + (c) * 32 + ch * 8);       \
        }                                                                        \
    }

    LOAD_TILE(0, 0);
    CP_COMMIT();

    for (int c = 0; c < KSPL_ / 32; c++) {
        const int buf = c & 1;
        if (c < KSPL_ / 32 - 1) {
            LOAD_TILE(1 - buf, c + 1);
            CP_COMMIT();
            CP_WAIT1();
        } else {
            CP_WAIT0();
        }
        __syncthreads();

#pragma unroll
        for (int kc = 0; kc < 2; kc++) {
            uint32_t afr[2][4], bfr[8][2];
#pragma unroll
            for (int mt = 0; mt < 2; mt++) {
                int row = wm0 + mt * 16 + (lane & 15);
                int ch  = kc * 2 + (lane >> 4);
                int ph  = ch ^ ((row >> 1) & 3);
                uint32_t addr = aBase[buf] + (row * 4 + ph) * 16;
                asm volatile("ldmatrix.sync.aligned.m8n8.x4.shared.b16 {%0,%1,%2,%3}, [%4];"
                             : "=r"(afr[mt][0]), "=r"(afr[mt][1]),
                               "=r"(afr[mt][2]), "=r"(afr[mt][3]) : "r"(addr));
            }
#pragma unroll
            for (int nt = 0; nt < 8; nt++) {
                int row = wn0 + nt * 8 + (lane & 7);
                int ch  = kc * 2 + ((lane >> 3) & 1);
                int ph  = ch ^ ((row >> 1) & 3);
                uint32_t addr = bBase[buf] + (row * 4 + ph) * 16;
                asm volatile("ldmatrix.sync.aligned.m8n8.x2.shared.b16 {%0,%1}, [%2];"
                             : "=r"(bfr[nt][0]), "=r"(bfr[nt][1]) : "r"(addr));
            }
#pragma unroll
            for (int mt = 0; mt < 2; mt++)
#pragma unroll
                for (int nt = 0; nt < 8; nt++) {
                    asm volatile(
                        "mma.sync.aligned.m16n8k16.row.col.f32.bf16.bf16.f32 "
                        "{%0,%1,%2,%3}, {%4,%5,%6,%7}, {%8,%9}, {%0,%1,%2,%3};"
                        : "+f"(acc[mt][nt][0]), "+f"(acc[mt][nt][1]),
                          "+f"(acc[mt][nt][2]), "+f"(acc[mt][nt][3])
                        : "r"(afr[mt][0]), "r"(afr[mt][1]), "r"(afr[mt][2]), "r"(afr[mt][3]),
                          "r"(bfr[nt][0]), "r"(bfr[nt][1]));
                }
        }
        __syncthreads();
    }

    // epilogue: c0,c1 at (row, col), c2,c3 at (row+8, col); col = 2*(lane%4)
#pragma unroll
    for (int mt = 0; mt < 2; mt++) {
#pragma unroll
        for (int nt = 0; nt < 8; nt++) {
            int row = wm0 + mt * 16 + (lane >> 2);
            int col = wn0 + nt * 8 + (lane & 3) * 2;
            int n = bn + col;
#pragma unroll
            for (int h = 0; h < 2; h++) {       // h=0: row, h=1: row+8
                int m = bm + row + h * 8;
                float vx = acc[mt][nt][h * 2 + 0];
                float vy = acc[mt][nt][h * 2 + 1];
                if (n + 1 < Nreal) {
                    float2 v;
                    v.x = vx; v.y = vy;
                    if (bias1) { v.x += bias1[n]; v.y += bias1[n + 1]; }
                    if (bias2) { v.x += bias2[n]; v.y += bias2[n + 1]; }
                    *(float2*)&C[(size_t)m * ldc + n] = v;
                } else if (n < Nreal) {
                    float v = vx;
                    if (bias1) v += bias1[n];
                    if (bias2) v += bias2[n];
                    C[(size_t)m * ldc + n] = v;
                }
            }
        }
    }
}

// ---------------- bf16 hi/lo split conversion ----------------------------
__global__ void cvt_split(const float* __restrict__ src, __nv_bfloat16* __restrict__ dst,
                          int rows_real, int rows_pad, int is_a)
{
    int i = blockIdx.x * blockDim.x + threadIdx.x;
    if (i >= rows_pad * 512) return;
    int r = i >> 9, k = i & 511;
    float a = (r < rows_real) ? src[(size_t)r * 512 + k] : 0.f;
    __nv_bfloat16 hi = __float2bfloat16(a);
    float lo = a - __bfloat162float(hi);
    __nv_bfloat16 lob = __float2bfloat16(lo);
    size_t b = (size_t)r * KSPL_;
    dst[b + k] = hi;
    dst[b + 512 + k]  = is_a ? hi : lob;
    dst[b + 1024 + k] = is_a ? lob : hi;
}

// ---------------- fp32 NT GEMM (scores only) ------------------------------
__global__ __launch_bounds__(256)
void sgemm_nt(const float* __restrict__ A, const float* __restrict__ Bm,
              float* __restrict__ C, int M, int N, int K,
              int sA, int sB, int sC)
{
    A  += (size_t)blockIdx.z * sA;
    Bm += (size_t)blockIdx.z * sB;
    C  += (size_t)blockIdx.z * sC;

    __shared__ float As[8][128];
    __shared__ float Bs[8][128];

    const int tid = threadIdx.x;
    const int bm  = blockIdx.y * 128;
    const int bn  = blockIdx.x * 128;
    const int lr  = tid >> 1;
    const int lc  = (tid & 1) * 4;
    const int ty  = tid >> 4;
    const int tx  = tid & 15;

    float acc[8][8];
#pragma unroll
    for (int i = 0; i < 8; i++)
#pragma unroll
        for (int j = 0; j < 8; j++) acc[i][j] = 0.f;

    for (int k0 = 0; k0 < K; k0 += 8) {
        float4 a4 = make_float4(0.f, 0.f, 0.f, 0.f);
        float4 b4 = make_float4(0.f, 0.f, 0.f, 0.f);
        if (bm + lr < M) a4 = *(const float4*)&A [(size_t)(bm + lr) * K + k0 + lc];
        if (bn + lr < N) b4 = *(const float4*)&Bm[(size_t)(bn + lr) * K + k0 + lc];
        __syncthreads();
        As[lc + 0][lr] = a4.x; As[lc + 1][lr] = a4.y;
        As[lc + 2][lr] = a4.z; As[lc + 3][lr] = a4.w;
        Bs[lc + 0][lr] = b4.x; Bs[lc + 1][lr] = b4.y;
        Bs[lc + 2][lr] = b4.z; Bs[lc + 3][lr] = b4.w;
        __syncthreads();
#pragma unroll
        for (int k = 0; k < 8; k++) {
            float ar[8], br[8];
            *(float4*)&ar[0] = *(const float4*)&As[k][ty * 8];
            *(float4*)&ar[4] = *(const float4*)&As[k][ty * 8 + 4];
            *(float4*)&br[0] = *(const float4*)&Bs[k][tx * 8];
            *(float4*)&br[4] = *(const float4*)&Bs[k][tx * 8 + 4];
#pragma unroll
            for (int i = 0; i < 8; i++)
#pragma unroll
                for (int j = 0; j < 8; j++)
                    acc[i][j] += ar[i] * br[j];
        }
    }

#pragma unroll
    for (int i = 0; i < 8; i++) {
        int mm = bm + ty * 8 + i;
        if (mm >= M) continue;
#pragma unroll
        for (int j = 0; j < 8; j++) {
            int n = bn + tx * 8 + j;
            if (n < N) C[(size_t)mm * N + n] = acc[i][j];
        }
    }
}

// ---------------- fc1 split-K --------------------------------------------
__global__ __launch_bounds__(256)
void fc1_part(const float* __restrict__ x, const float* __restrict__ w)
{
    const int nt = blockIdx.x, kt = blockIdx.y;
    __shared__ float xs[64][68];
    __shared__ float ws[64][68];
    const int tid = threadIdx.x;
    const int ty = tid >> 4, tx = tid & 15;

    float acc[4][4];
#pragma unroll
    for (int i = 0; i < 4; i++)
#pragma unroll
        for (int j = 0; j < 4; j++) acc[i][j] = 0.f;

    for (int kc = 0; kc < 4; kc++) {
        int k0 = kt * 256 + kc * 64;
        for (int i = tid; i < 64 * 16; i += 256) {
            int r = i >> 4, c4 = (i & 15) * 4;
            *(float4*)&xs[r][c4] = *(const float4*)&x[(size_t)r * ENC_ + k0 + c4];
            *(float4*)&ws[r][c4] = *(const float4*)&w[(size_t)(nt * 64 + r) * ENC_ + k0 + c4];
        }
        __syncthreads();
#pragma unroll 8
        for (int k = 0; k < 64; k++) {
            float a[4], b[4];
#pragma unroll
            for (int i = 0; i < 4; i++) a[i] = xs[ty * 4 + i][k];
#pragma unroll
            for (int j = 0; j < 4; j++) b[j] = ws[tx * 4 + j][k];
#pragma unroll
            for (int i = 0; i < 4; i++)
#pragma unroll
                for (int j = 0; j < 4; j++) acc[i][j] += a[i] * b[j];
        }
        __syncthreads();
    }
#pragma unroll
    for (int i = 0; i < 4; i++)
#pragma unroll
        for (int j = 0; j < 4; j++)
            g_fc1p[((size_t)kt * B_ + ty * 4 + i) * EMB_ + nt * 64 + tx * 4 + j] = acc[i][j];
}

__global__ void fc1_reduce(const float* __restrict__ b1)
{
    int b = blockIdx.x, j = threadIdx.x;
    float s = b1[j];
#pragma unroll
    for (int kt = 0; kt < 8; kt++) s += g_fc1p[((size_t)kt * B_ + b) * EMB_ + j];
    g_feat[b * EMB_ + j] = s;
}

// ---------------- batchnorm + write seq[:,0,:] ----------------------------
__global__ void bn_k(const float* __restrict__ gamma, const float* __restrict__ beta)
{
    int j = blockIdx.x;
    int b = threadIdx.x;
    float v = g_feat[b * EMB_ + j];
    __shared__ float s1[64], s2[64];
    s1[b] = v; s2[b] = v * v;
    __syncthreads();
    for (int off = 32; off > 0; off >>= 1) {
        if (b < off) { s1[b] += s1[b + off]; s2[b] += s2[b + off]; }
        __syncthreads();
    }
    float mu  = s1[0] * (1.f / 64.f);
    float var = s2[0] * (1.f / 64.f) - mu * mu;
    float r   = rsqrtf(var + 1e-5f);
    g_seq[(size_t)b * S_ * EMB_ + j] = (v - mu) * r * gamma[j] + beta[j];
}

// ---------------- embedding gather ----------------------------------------
__global__ void embed_k(const int* __restrict__ y, const float* __restrict__ emb)
{
    int i = blockIdx.x * blockDim.x + threadIdx.x;
    if (i >= B_ * T_ * (EMB_ / 4)) return;
    int d4 = i & 127;
    int bt = i >> 7;
    int tt = bt % T_;
    int b  = bt / T_;
    int tok = y[b * T_ + tt];
    ((float4*)g_seq)[(size_t)(b * S_ + 1 + tt) * (EMB_ / 4) + d4] =
        ((const float4*)emb)[(size_t)tok * (EMB_ / 4) + d4];
}

// ---------------- zero h0/c0/barrier --------------------------------------
__global__ void zero_k()
{
    int i = blockIdx.x * blockDim.x + threadIdx.x;
    if (i < B_ * HID_) { g_h[0][i] = 0.f; g_c[i] = 0.f; }
    if (i == 0) g_bar = 0u;
}

// ---------------- persistent LSTM (validated) ------------------------------
#define WS_STRIDE 516
__global__ __launch_bounds__(256)
void lstm_all(const float* __restrict__ w_hh, const int* __restrict__ lengths)
{
    extern __shared__ float sm[];
    float* ws  = sm;
    float* hs  = ws + 16 * WS_STRIDE;
    float* red = hs + 64 * WS_STRIDE;

    const int tid = threadIdx.x;
    const int j0  = blockIdx.x * 4;

    for (int i = tid; i < 16 * 128; i += 256) {
        int k4 = i & 127, r = i >> 7;
        int g = r >> 2, jl = r & 3;
        *(float4*)&ws[r * WS_STRIDE + k4 * 4] =
            *(const float4*)(w_hh + (size_t)(g * HID_ + j0 + jl) * HID_ + k4 * 4);
    }

    const int ks  = tid >> 6;
    const int sub = tid & 63;
    const int jl  = sub >> 4;
    const int b0  = (sub & 15) * 4;
    const int j   = j0 + jl;

    volatile unsigned* vbar = &g_bar;

    float creg[4];
    if (ks == 0) {
#pragma unroll
        for (int bi = 0; bi < 4; bi++) creg[bi] = 0.f;
    }

    __syncthreads();

    for (int t = 0; t < S_; t++) {
        if (tid == 0) {
            unsigned target = 128u * (unsigned)t;
            while (*vbar < target) { }
        }
        __syncthreads();

        const float4* h_in4 = (const float4*)g_h[t & 1];
#pragma unroll 8
        for (int i = tid; i < 64 * 128; i += 256) {
            int b  = i >> 7;
            int k4 = i & 127;
            float4 v = __ldcv(&h_in4[i]);
            *(float4*)&hs[b * WS_STRIDE + k4 * 4] = v;
        }
        __syncthreads();

        float acc[4][4];
        if (ks == 0) {
#pragma unroll
            for (int bi = 0; bi < 4; bi++)
#pragma unroll
                for (int g = 0; g < 4; g++)
                    acc[bi][g] = g_xw[((size_t)(b0 + bi) * S_ + t) * (4 * HID_) + g * HID_ + j];
        } else {
#pragma unroll
            for (int bi = 0; bi < 4; bi++)
#pragma unroll
                for (int g = 0; g < 4; g++) acc[bi][g] = 0.f;
        }

        const int kbeg = ks * 128;
#pragma unroll 4
        for (int k = kbeg; k < kbeg + 128; k += 4) {
            float4 w4[4];
#pragma unroll
            for (int g = 0; g < 4; g++)
                w4[g] = *(const float4*)&ws[(g * 4 + jl) * WS_STRIDE + k];
#pragma unroll
            for (int bi = 0; bi < 4; bi++) {
                float4 h4 = *(const float4*)&hs[(b0 + bi) * WS_STRIDE + k];
#pragma unroll
                for (int g = 0; g < 4; g++)
                    acc[bi][g] += h4.x * w4[g].x + h4.y * w4[g].y
                                + h4.z * w4[g].z + h4.w * w4[g].w;
            }
        }

        if (ks > 0) {
#pragma unroll
            for (int bi = 0; bi < 4; bi++)
#pragma unroll
                for (int g = 0; g < 4; g++)
                    red[(((ks - 1) * 64 + sub) * 16) + bi * 4 + g] = acc[bi][g];
        }
        __syncthreads();

        if (ks == 0) {
            float* h_out = g_h[(t + 1) & 1];
#pragma unroll
            for (int bi = 0; bi < 4; bi++) {
                int bb = b0 + bi;
                float vi = acc[bi][0], vf = acc[bi][1], vg = acc[bi][2], vo = acc[bi][3];
#pragma unroll
                for (int r = 0; r < 3; r++) {
                    vi += red[((r * 64 + sub) * 16) + bi * 4 + 0];
                    vf += red[((r * 64 + sub) * 16) + bi * 4 + 1];
                    vg += red[((r * 64 + sub) * 16) + bi * 4 + 2];
                    vo += red[((r * 64 + sub) * 16) + bi * 4 + 3];
                }
                float gi = sigmoidf_(vi);
                float gf = sigmoidf_(vf);
                float gg = tanhf(vg);
                float go = sigmoidf_(vo);
                float c  = gf * creg[bi] + gi * gg;
                creg[bi] = c;
                float h = go * tanhf(c);
                h_out[bb * HID_ + j] = h;
                g_out[((size_t)bb * S_ + t) * HID_ + j] = (t < lengths[bb]) ? h : 0.f;
            }
            __threadfence();
        }
        __syncthreads();
        if (tid == 0) atomicAdd(&g_bar, 1u);
    }
}

// ---------------- softmax (reference zero-mask semantics) -----------------
__global__ void softmax_mask()
{
    int w    = threadIdx.x >> 5;
    int lane = threadIdx.x & 31;
    int row  = blockIdx.x * 4 + w;
    int t    = row & (S_ - 1);
    float* sc = g_sc + (size_t)row * S_;

    float v[4];
#pragma unroll
    for (int u = 0; u < 4; u++) {
        int s = lane + u * 32;
        float x = sc[s];
        v[u] = (s < t) ? x : 0.f;
    }
    float m = fmaxf(fmaxf(v[0], v[1]), fmaxf(v[2], v[3]));
#pragma unroll
    for (int off = 16; off > 0; off >>= 1)
        m = fmaxf(m, __shfl_xor_sync(0xffffffffu, m, off));
    float e[4], sum = 0.f;
#pragma unroll
    for (int u = 0; u < 4; u++) { e[u] = expf(v[u] - m); sum += e[u]; }
#pragma unroll
    for (int off = 16; off > 0; off >>= 1)
        sum += __shfl_xor_sync(0xffffffffu, sum, off);
    float inv = 1.f / sum;
#pragma unroll
    for (int u = 0; u < 4; u++) {
        int s = lane + u * 32;
        sc[s] = (s < t) ? e[u] * inv : 0.f;
    }
}

// ---------------- attn = (alpha*mask) @ out -------------------------------
__global__ __launch_bounds__(256)
void attn_mm()
{
    int b  = blockIdx.y;
    int t0 = blockIdx.x * 16;
    __shared__ float al[16][128];
    int tid = threadIdx.x;
    for (int i = tid; i < 16 * 128; i += 256)
        al[i >> 7][i & 127] = g_sc[((size_t)b * S_ + t0 + (i >> 7)) * S_ + (i & 127)];
    __syncthreads();

    int d0 = tid * 2;
    float2 acc[16];
#pragma unroll
    for (int t = 0; t < 16; t++) acc[t] = make_float2(0.f, 0.f);

    for (int s = 0; s < 128; s++) {
        float2 o = *(const float2*)&g_out[((size_t)b * S_ + s) * HID_ + d0];
#pragma unroll
        for (int t = 0; t < 16; t++) {
            float a = al[t][s];
            acc[t].x += a * o.x;
            acc[t].y += a * o.y;
        }
    }
#pragma unroll
    for (int t = 0; t < 16; t++)
        *(float2*)&g_attn[((size_t)b * S_ + t0 + t) * HID_ + d0] = acc[t];
}

// ---------------- launch --------------------------------------------------
extern "C" void kernel_launch(void* const* d_in, const int* in_sizes, int n_in,
                              void* d_out, int out_size)
{
    const float* x      = (const float*)d_in[0];
    const int*   y      = (const int*)  d_in[1];
    const int*   len    = (const int*)  d_in[2];
    const float* fc1_w  = (const float*)d_in[3];
    const float* fc1_b  = (const float*)d_in[4];
    const float* bn_g   = (const float*)d_in[5];
    const float* bn_b   = (const float*)d_in[6];
    const float* emb    = (const float*)d_in[7];
    const float* w_ih   = (const float*)d_in[8];
    const float* w_hh   = (const float*)d_in[9];
    const float* b_ih   = (const float*)d_in[10];
    const float* b_hh   = (const float*)d_in[11];
    const float* fc2_w  = (const float*)d_in[12];
    const float* fc2_b  = (const float*)d_in[13];
    float* out = (float*)d_out;

    float *p_seq, *p_xw, *p_out, *p_sc, *p_attn;
    __nv_bfloat16 *p_abf, *p_wbf, *p_sbf, *p_wihbf;
    cudaGetSymbolAddress((void**)&p_seq,   g_seq);
    cudaGetSymbolAddress((void**)&p_xw,    g_xw);
    cudaGetSymbolAddress((void**)&p_out,   g_out);
    cudaGetSymbolAddress((void**)&p_sc,    g_sc);
    cudaGetSymbolAddress((void**)&p_attn,  g_attn);
    cudaGetSymbolAddress((void**)&p_abf,   g_abf);
    cudaGetSymbolAddress((void**)&p_wbf,   g_wbf);
    cudaGetSymbolAddress((void**)&p_sbf,   g_sbf);
    cudaGetSymbolAddress((void**)&p_wihbf, g_wihbf);

    const int LSTM_SMEM = (16 * WS_STRIDE + 64 * WS_STRIDE + 3 * 64 * 16) * 4;
    cudaFuncSetAttribute(lstm_all, cudaFuncAttributeMaxDynamicSharedMemorySize, LSTM_SMEM);

    // fc1 + bn + embedding
    fc1_part<<<dim3(8, 8), 256>>>(x, fc1_w);
    fc1_reduce<<<64, 512>>>(fc1_b);
    bn_k<<<EMB_, 64>>>(bn_g, bn_b);
    embed_k<<<(B_ * T_ * (EMB_ / 4) + 255) / 256, 256>>>(y, emb);

    // xW = seq @ w_ih^T + b_ih + b_hh  (bf16 3-term warp-MMA)
    cvt_split<<<(MS_ * 512 + 255) / 256, 256>>>(p_seq, p_sbf, MS_, MS_, 1);
    cvt_split<<<(2048 * 512 + 255) / 256, 256>>>(w_ih, p_wihbf, 2048, 2048, 0);
    bf16_gemm_mma<<<dim3(16, 64), 256>>>(p_sbf, p_wihbf, b_ih, b_hh,
                                         p_xw, 2048, 2048);

    // recurrent LSTM
    zero_k<<<128, 256>>>();
    lstm_all<<<128, 256, LSTM_SMEM>>>(w_hh, len);

    // attention
    sgemm_nt<<<dim3(1, 1, B_), 256>>>(p_out, p_out, p_sc,
                                      S_, S_, HID_, S_ * HID_, S_ * HID_, S_ * S_);
    softmax_mask<<<MS_ / 4, 128>>>();
    attn_mm<<<dim3(8, B_), 256>>>();

    // predictions = attn @ fc2_w^T + fc2_b  (bf16 3-term warp-MMA)
    cvt_split<<<(MS_ * 512 + 255) / 256, 256>>>(p_attn, p_abf, MS_, MS_, 1);
    cvt_split<<<(VPAD_ * 512 + 255) / 256, 256>>>(fc2_w, p_wbf, VOCAB_, VPAD_, 0);
    bf16_gemm_mma<<<dim3(79, 64), 256>>>(p_abf, p_wbf, fc2_b, nullptr,
                                         out, VOCAB_, VOCAB_);
}

// round 7
// speedup vs baseline: 2.9298x; 1.4266x over previous
#include <cuda_runtime.h>
#include <cuda_bf16.h>
#include <math.h>
#include <stdint.h>

#define B_     64
#define T_     127
#define S_     128
#define ENC_   2048
#define EMB_   512
#define HID_   512
#define VOCAB_ 10000
#define MS_    (B_*S_)          // 8192
#define VPAD_  10112            // 79*128
#define KSPL_  1536             // 3*512 split-K' for bf16 3-term GEMM

// ---------------- static scratch (no cudaMalloc allowed) ----------------
__device__ float g_fc1p[8*B_*EMB_];
__device__ float g_feat[B_*EMB_];
__device__ float g_seq [B_*S_*EMB_];
__device__ float g_xw  [B_*S_*4*HID_];
__device__ float g_out [B_*S_*HID_];
__device__ float g_sc  [B_*S_*S_];
__device__ float g_attn[B_*S_*HID_];
__device__ unsigned g_bar;
__device__ __nv_bfloat16 g_hh[2][B_*HID_];        // h hi (bf16), double buffered
__device__ __nv_bfloat16 g_hl[2][B_*HID_];        // h lo (bf16)
__device__ __nv_bfloat16 g_abf  [MS_  * KSPL_];   // attn split  [Ah|Ah|Al]
__device__ __nv_bfloat16 g_wbf  [VPAD_* KSPL_];   // fc2_w split [Bh|Bl|Bh]
__device__ __nv_bfloat16 g_sbf  [MS_  * KSPL_];   // seq split
__device__ __nv_bfloat16 g_wihbf[2048 * KSPL_];   // w_ih split

__device__ __forceinline__ float sigmoidf_(float x) { return 1.f / (1.f + expf(-x)); }

__device__ __forceinline__ uint32_t smem_u32(const void* p) {
    uint32_t a;
    asm("{ .reg .u64 t; cvta.to.shared.u64 t, %1; cvt.u32.u64 %0, t; }" : "=r"(a) : "l"(p));
    return a;
}
#define CP_ASYNC16(dst, src) asm volatile("cp.async.cg.shared.global [%0], [%1], 16;" :: "r"(dst), "l"(src) : "memory")
#define CP_COMMIT()          asm volatile("cp.async.commit_group;" ::: "memory")
#define CP_WAIT1()           asm volatile("cp.async.wait_group 1;" ::: "memory")
#define CP_WAIT0()           asm volatile("cp.async.wait_group 0;" ::: "memory")

#define MMA_BF16(acc, a0, a1, a2, a3, b0, b1)                                    \
    asm volatile(                                                                \
        "mma.sync.aligned.m16n8k16.row.col.f32.bf16.bf16.f32 "                   \
        "{%0,%1,%2,%3}, {%4,%5,%6,%7}, {%8,%9}, {%0,%1,%2,%3};"                  \
        : "+f"(acc[0]), "+f"(acc[1]), "+f"(acc[2]), "+f"(acc[3])                 \
        : "r"(a0), "r"(a1), "r"(a2), "r"(a3), "r"(b0), "r"(b1))

// ============ bf16 warp-MMA NT GEMM (validated round 6) ===================
__global__ __launch_bounds__(256)
void bf16_gemm_mma(const __nv_bfloat16* __restrict__ A,
                   const __nv_bfloat16* __restrict__ Bm,
                   const float* __restrict__ bias1,
                   const float* __restrict__ bias2,
                   float* __restrict__ C, int Nreal, int ldc)
{
    __shared__ __align__(16) __nv_bfloat16 sA[2][128 * 32];
    __shared__ __align__(16) __nv_bfloat16 sB[2][128 * 32];

    const int tid  = threadIdx.x;
    const int warp = tid >> 5;
    const int lane = tid & 31;
    const int wm0  = (warp & 3) * 32;
    const int wn0  = (warp >> 2) * 64;
    const int bm   = blockIdx.y * 128;
    const int bn   = blockIdx.x * 128;

    const uint32_t aBase[2] = { smem_u32(&sA[0][0]), smem_u32(&sA[1][0]) };
    const uint32_t bBase[2] = { smem_u32(&sB[0][0]), smem_u32(&sB[1][0]) };

    float acc[2][8][4];
#pragma unroll
    for (int mt = 0; mt < 2; mt++)
#pragma unroll
        for (int nt = 0; nt < 8; nt++)
#pragma unroll
            for (int u = 0; u < 4; u++) acc[mt][nt][u] = 0.f;

    const int idx0 = tid * 2;

#define LOAD_TILE(buf, c)                                                        \
    {                                                                            \
        _Pragma("unroll")                                                        \
        for (int u = 0; u < 2; u++) {                                            \
            int idx = idx0 + u;                                                  \
            int r = idx >> 2, ch = idx & 3;                                      \
            int ph = ch ^ ((r >> 1) & 3);                                        \
            CP_ASYNC16(aBase[buf] + (r * 4 + ph) * 16,                           \
                       A + (size_t)(bm + r) * KSPL_ + (c) * 32 + ch * 8);        \
            CP_ASYNC16(bBase[buf] + (r * 4 + ph) * 16,                           \
                       Bm + (size_t)(bn + r) * KSPL_ + (c) * 32 + ch * 8);       \
        }                                                                        \
    }

    LOAD_TILE(0, 0);
    CP_COMMIT();

    for (int c = 0; c < KSPL_ / 32; c++) {
        const int buf = c & 1;
        if (c < KSPL_ / 32 - 1) {
            LOAD_TILE(1 - buf, c + 1);
            CP_COMMIT();
            CP_WAIT1();
        } else {
            CP_WAIT0();
        }
        __syncthreads();

#pragma unroll
        for (int kc = 0; kc < 2; kc++) {
            uint32_t afr[2][4], bfr[8][2];
#pragma unroll
            for (int mt = 0; mt < 2; mt++) {
                int row = wm0 + mt * 16 + (lane & 15);
                int ch  = kc * 2 + (lane >> 4);
                int ph  = ch ^ ((row >> 1) & 3);
                uint32_t addr = aBase[buf] + (row * 4 + ph) * 16;
                asm volatile("ldmatrix.sync.aligned.m8n8.x4.shared.b16 {%0,%1,%2,%3}, [%4];"
                             : "=r"(afr[mt][0]), "=r"(afr[mt][1]),
                               "=r"(afr[mt][2]), "=r"(afr[mt][3]) : "r"(addr));
            }
#pragma unroll
            for (int nt = 0; nt < 8; nt++) {
                int row = wn0 + nt * 8 + (lane & 7);
                int ch  = kc * 2 + ((lane >> 3) & 1);
                int ph  = ch ^ ((row >> 1) & 3);
                uint32_t addr = bBase[buf] + (row * 4 + ph) * 16;
                asm volatile("ldmatrix.sync.aligned.m8n8.x2.shared.b16 {%0,%1}, [%2];"
                             : "=r"(bfr[nt][0]), "=r"(bfr[nt][1]) : "r"(addr));
            }
#pragma unroll
            for (int mt = 0; mt < 2; mt++)
#pragma unroll
                for (int nt = 0; nt < 8; nt++)
                    MMA_BF16(acc[mt][nt], afr[mt][0], afr[mt][1], afr[mt][2], afr[mt][3],
                             bfr[nt][0], bfr[nt][1]);
        }
        __syncthreads();
    }

#pragma unroll
    for (int mt = 0; mt < 2; mt++) {
#pragma unroll
        for (int nt = 0; nt < 8; nt++) {
            int row = wm0 + mt * 16 + (lane >> 2);
            int col = wn0 + nt * 8 + (lane & 3) * 2;
            int n = bn + col;
#pragma unroll
            for (int h = 0; h < 2; h++) {
                int m = bm + row + h * 8;
                float vx = acc[mt][nt][h * 2 + 0];
                float vy = acc[mt][nt][h * 2 + 1];
                if (n + 1 < Nreal) {
                    float2 v;
                    v.x = vx; v.y = vy;
                    if (bias1) { v.x += bias1[n]; v.y += bias1[n + 1]; }
                    if (bias2) { v.x += bias2[n]; v.y += bias2[n + 1]; }
                    *(float2*)&C[(size_t)m * ldc + n] = v;
                } else if (n < Nreal) {
                    float v = vx;
                    if (bias1) v += bias1[n];
                    if (bias2) v += bias2[n];
                    C[(size_t)m * ldc + n] = v;
                }
            }
        }
    }
}

// ---------------- bf16 hi/lo split conversion ----------------------------
__global__ void cvt_split(const float* __restrict__ src, __nv_bfloat16* __restrict__ dst,
                          int rows_real, int rows_pad, int is_a)
{
    int i = blockIdx.x * blockDim.x + threadIdx.x;
    if (i >= rows_pad * 512) return;
    int r = i >> 9, k = i & 511;
    float a = (r < rows_real) ? src[(size_t)r * 512 + k] : 0.f;
    __nv_bfloat16 hi = __float2bfloat16(a);
    float lo = a - __bfloat162float(hi);
    __nv_bfloat16 lob = __float2bfloat16(lo);
    size_t b = (size_t)r * KSPL_;
    dst[b + k] = hi;
    dst[b + 512 + k]  = is_a ? hi : lob;
    dst[b + 1024 + k] = is_a ? lob : hi;
}

// ---------------- fp32 NT GEMM (scores only) ------------------------------
__global__ __launch_bounds__(256)
void sgemm_nt(const float* __restrict__ A, const float* __restrict__ Bm,
              float* __restrict__ C, int M, int N, int K,
              int sA, int sB, int sC)
{
    A  += (size_t)blockIdx.z * sA;
    Bm += (size_t)blockIdx.z * sB;
    C  += (size_t)blockIdx.z * sC;

    __shared__ float As[8][128];
    __shared__ float Bs[8][128];

    const int tid = threadIdx.x;
    const int bm  = blockIdx.y * 128;
    const int bn  = blockIdx.x * 128;
    const int lr  = tid >> 1;
    const int lc  = (tid & 1) * 4;
    const int ty  = tid >> 4;
    const int tx  = tid & 15;

    float acc[8][8];
#pragma unroll
    for (int i = 0; i < 8; i++)
#pragma unroll
        for (int j = 0; j < 8; j++) acc[i][j] = 0.f;

    for (int k0 = 0; k0 < K; k0 += 8) {
        float4 a4 = make_float4(0.f, 0.f, 0.f, 0.f);
        float4 b4 = make_float4(0.f, 0.f, 0.f, 0.f);
        if (bm + lr < M) a4 = *(const float4*)&A [(size_t)(bm + lr) * K + k0 + lc];
        if (bn + lr < N) b4 = *(const float4*)&Bm[(size_t)(bn + lr) * K + k0 + lc];
        __syncthreads();
        As[lc + 0][lr] = a4.x; As[lc + 1][lr] = a4.y;
        As[lc + 2][lr] = a4.z; As[lc + 3][lr] = a4.w;
        Bs[lc + 0][lr] = b4.x; Bs[lc + 1][lr] = b4.y;
        Bs[lc + 2][lr] = b4.z; Bs[lc + 3][lr] = b4.w;
        __syncthreads();
#pragma unroll
        for (int k = 0; k < 8; k++) {
            float ar[8], br[8];
            *(float4*)&ar[0] = *(const float4*)&As[k][ty * 8];
            *(float4*)&ar[4] = *(const float4*)&As[k][ty * 8 + 4];
            *(float4*)&br[0] = *(const float4*)&Bs[k][tx * 8];
            *(float4*)&br[4] = *(const float4*)&Bs[k][tx * 8 + 4];
#pragma unroll
            for (int i = 0; i < 8; i++)
#pragma unroll
                for (int j = 0; j < 8; j++)
                    acc[i][j] += ar[i] * br[j];
        }
    }

#pragma unroll
    for (int i = 0; i < 8; i++) {
        int mm = bm + ty * 8 + i;
        if (mm >= M) continue;
#pragma unroll
        for (int j = 0; j < 8; j++) {
            int n = bn + tx * 8 + j;
            if (n < N) C[(size_t)mm * N + n] = acc[i][j];
        }
    }
}

// ---------------- fc1 split-K --------------------------------------------
__global__ __launch_bounds__(256)
void fc1_part(const float* __restrict__ x, const float* __restrict__ w)
{
    const int nt = blockIdx.x, kt = blockIdx.y;
    __shared__ float xs[64][68];
    __shared__ float ws[64][68];
    const int tid = threadIdx.x;
    const int ty = tid >> 4, tx = tid & 15;

    float acc[4][4];
#pragma unroll
    for (int i = 0; i < 4; i++)
#pragma unroll
        for (int j = 0; j < 4; j++) acc[i][j] = 0.f;

    for (int kc = 0; kc < 4; kc++) {
        int k0 = kt * 256 + kc * 64;
        for (int i = tid; i < 64 * 16; i += 256) {
            int r = i >> 4, c4 = (i & 15) * 4;
            *(float4*)&xs[r][c4] = *(const float4*)&x[(size_t)r * ENC_ + k0 + c4];
            *(float4*)&ws[r][c4] = *(const float4*)&w[(size_t)(nt * 64 + r) * ENC_ + k0 + c4];
        }
        __syncthreads();
#pragma unroll 8
        for (int k = 0; k < 64; k++) {
            float a[4], b[4];
#pragma unroll
            for (int i = 0; i < 4; i++) a[i] = xs[ty * 4 + i][k];
#pragma unroll
            for (int j = 0; j < 4; j++) b[j] = ws[tx * 4 + j][k];
#pragma unroll
            for (int i = 0; i < 4; i++)
#pragma unroll
                for (int j = 0; j < 4; j++) acc[i][j] += a[i] * b[j];
        }
        __syncthreads();
    }
#pragma unroll
    for (int i = 0; i < 4; i++)
#pragma unroll
        for (int j = 0; j < 4; j++)
            g_fc1p[((size_t)kt * B_ + ty * 4 + i) * EMB_ + nt * 64 + tx * 4 + j] = acc[i][j];
}

__global__ void fc1_reduce(const float* __restrict__ b1)
{
    int b = blockIdx.x, j = threadIdx.x;
    float s = b1[j];
#pragma unroll
    for (int kt = 0; kt < 8; kt++) s += g_fc1p[((size_t)kt * B_ + b) * EMB_ + j];
    g_feat[b * EMB_ + j] = s;
}

// ---------------- batchnorm + write seq[:,0,:] ----------------------------
__global__ void bn_k(const float* __restrict__ gamma, const float* __restrict__ beta)
{
    int j = blockIdx.x;
    int b = threadIdx.x;
    float v = g_feat[b * EMB_ + j];
    __shared__ float s1[64], s2[64];
    s1[b] = v; s2[b] = v * v;
    __syncthreads();
    for (int off = 32; off > 0; off >>= 1) {
        if (b < off) { s1[b] += s1[b + off]; s2[b] += s2[b + off]; }
        __syncthreads();
    }
    float mu  = s1[0] * (1.f / 64.f);
    float var = s2[0] * (1.f / 64.f) - mu * mu;
    float r   = rsqrtf(var + 1e-5f);
    g_seq[(size_t)b * S_ * EMB_ + j] = (v - mu) * r * gamma[j] + beta[j];
}

// ---------------- embedding gather ----------------------------------------
__global__ void embed_k(const int* __restrict__ y, const float* __restrict__ emb)
{
    int i = blockIdx.x * blockDim.x + threadIdx.x;
    if (i >= B_ * T_ * (EMB_ / 4)) return;
    int d4 = i & 127;
    int bt = i >> 7;
    int tt = bt % T_;
    int b  = bt / T_;
    int tok = y[b * T_ + tt];
    ((float4*)g_seq)[(size_t)(b * S_ + 1 + tt) * (EMB_ / 4) + d4] =
        ((const float4*)emb)[(size_t)tok * (EMB_ / 4) + d4];
}

// ---------------- zero h0 (bf16 hi/lo) / barrier --------------------------
__global__ void zero_k()
{
    int i = blockIdx.x * blockDim.x + threadIdx.x;
    if (i < B_ * HID_ / 2) {
        ((uint32_t*)&g_hh[0][0])[i] = 0u;
        ((uint32_t*)&g_hl[0][0])[i] = 0u;
    }
    if (i == 0) g_bar = 0u;
}

// ---------------- persistent LSTM with bf16 mma recurrent matvec ----------
// 128 blocks x 256 threads, 1/SM. Block owns 4 h-cols (16 W-rows: r=g*4+jl).
// W split hi/lo into smem once. Per step: stage h hi/lo via cp.async.cg,
// 3 mma passes (Ah*Wh, Ah*Wl, Al*Wh), gate exchange in smem, cell update
// with c in registers, h written as bf16 hi/lo for next step.
#define LW_STRIDE 520           // bf16 per row (512 + 8 pad) = 1040B = 65 chunks
__global__ __launch_bounds__(256)
void lstm_mma(const float* __restrict__ w_hh, const int* __restrict__ lengths)
{
    extern __shared__ __align__(16) char smraw[];
    __nv_bfloat16* Wh = (__nv_bfloat16*)smraw;                  // 16 x 520
    __nv_bfloat16* Wl = Wh + 16 * LW_STRIDE;
    __nv_bfloat16* Ahs = Wl + 16 * LW_STRIDE;                   // 64 x 520
    __nv_bfloat16* Als = Ahs + 64 * LW_STRIDE;
    float* sg = (float*)(Als + 64 * LW_STRIDE);                 // 64 x 17

    const int tid  = threadIdx.x;
    const int warp = tid >> 5;
    const int lane = tid & 31;
    const int j0   = blockIdx.x * 4;

    // split W rows r = g*4+jl <- w_hh[g*512 + j0+jl][:]
    for (int i = tid; i < 16 * 512; i += 256) {
        int r = i >> 9, k = i & 511;
        int g = r >> 2, jl = r & 3;
        float w = w_hh[(size_t)(g * HID_ + j0 + jl) * HID_ + k];
        __nv_bfloat16 hi = __float2bfloat16(w);
        float lo = w - __bfloat162float(hi);
        Wh[r * LW_STRIDE + k] = hi;
        Wl[r * LW_STRIDE + k] = __float2bfloat16(lo);
    }

    const uint32_t ahA = smem_u32(Ahs), alA = smem_u32(Als);
    const uint32_t whA = smem_u32(Wh),  wlA = smem_u32(Wl);

    const int mt = warp & 3;        // M tile: batches mt*16..
    const int nh = warp >> 2;       // N half: W-rows nh*8..

    const int cb  = tid >> 2;       // cell-update batch
    const int cj  = tid & 3;        // cell-update jl
    const int len = lengths[cb];
    float creg = 0.f;

    volatile unsigned* vbar = &g_bar;
    __syncthreads();

    for (int t = 0; t < S_; t++) {
        if (tid == 0) {
            unsigned target = 128u * (unsigned)t;
            while (*vbar < target) { }
        }
        __syncthreads();

        // stage h hi (group A) then h lo (group B). 4096 16B chunks each.
        const char* hh = (const char*)g_hh[t & 1];
        const char* hl = (const char*)g_hl[t & 1];
#pragma unroll
        for (int u = 0; u < 16; u++) {
            int idx = tid + u * 256;
            int b = idx >> 6, c = idx & 63;
            CP_ASYNC16(ahA + (uint32_t)(b * 65 + c) * 16, hh + b * 1024 + c * 16);
        }
        CP_COMMIT();
#pragma unroll
        for (int u = 0; u < 16; u++) {
            int idx = tid + u * 256;
            int b = idx >> 6, c = idx & 63;
            CP_ASYNC16(alA + (uint32_t)(b * 65 + c) * 16, hl + b * 1024 + c * 16);
        }
        CP_COMMIT();

        float acc[4] = {0.f, 0.f, 0.f, 0.f};

        CP_WAIT1();           // Ah resident
        __syncthreads();

        const int arow0 = mt * 16 + (lane & 15);
        const int asel  = lane >> 4;
        const int brow0 = nh * 8 + (lane & 7);
        const int bsel  = (lane >> 3) & 1;

        // passes 1-2: Ah * Wh, Ah * Wl
#pragma unroll
        for (int pass = 0; pass < 2; pass++) {
            uint32_t bB = pass ? wlA : whA;
#pragma unroll 8
            for (int kk = 0; kk < 32; kk++) {
                uint32_t a0, a1, a2, a3, b0, b1;
                uint32_t aaddr = ahA + (uint32_t)(arow0 * 65 + kk * 2 + asel) * 16;
                asm volatile("ldmatrix.sync.aligned.m8n8.x4.shared.b16 {%0,%1,%2,%3}, [%4];"
                             : "=r"(a0), "=r"(a1), "=r"(a2), "=r"(a3) : "r"(aaddr));
                uint32_t baddr = bB + (uint32_t)(brow0 * 65 + kk * 2 + bsel) * 16;
                asm volatile("ldmatrix.sync.aligned.m8n8.x2.shared.b16 {%0,%1}, [%2];"
                             : "=r"(b0), "=r"(b1) : "r"(baddr));
                MMA_BF16(acc, a0, a1, a2, a3, b0, b1);
            }
        }

        CP_WAIT0();           // Al resident
        __syncthreads();

        // pass 3: Al * Wh
#pragma unroll 8
        for (int kk = 0; kk < 32; kk++) {
            uint32_t a0, a1, a2, a3, b0, b1;
            uint32_t aaddr = alA + (uint32_t)(arow0 * 65 + kk * 2 + asel) * 16;
            asm volatile("ldmatrix.sync.aligned.m8n8.x4.shared.b16 {%0,%1,%2,%3}, [%4];"
                         : "=r"(a0), "=r"(a1), "=r"(a2), "=r"(a3) : "r"(aaddr));
            uint32_t baddr = whA + (uint32_t)(brow0 * 65 + kk * 2 + bsel) * 16;
            asm volatile("ldmatrix.sync.aligned.m8n8.x2.shared.b16 {%0,%1}, [%2];"
                         : "=r"(b0), "=r"(b1) : "r"(baddr));
            MMA_BF16(acc, a0, a1, a2, a3, b0, b1);
        }

        // epilogue: acc -> sg[batch][wrow]
        {
            int row = mt * 16 + (lane >> 2);
            int col = nh * 8 + (lane & 3) * 2;
            sg[row * 17 + col]           = acc[0];
            sg[row * 17 + col + 1]       = acc[1];
            sg[(row + 8) * 17 + col]     = acc[2];
            sg[(row + 8) * 17 + col + 1] = acc[3];
        }
        __syncthreads();

        // cell update: thread (cb, cj)
        {
            const float* xwp = g_xw + ((size_t)cb * S_ + t) * (4 * HID_) + j0 + cj;
            float vi = sg[cb * 17 + 0 * 4 + cj] + xwp[0 * HID_];
            float vf = sg[cb * 17 + 1 * 4 + cj] + xwp[1 * HID_];
            float vg = sg[cb * 17 + 2 * 4 + cj] + xwp[2 * HID_];
            float vo = sg[cb * 17 + 3 * 4 + cj] + xwp[3 * HID_];
            float gi = sigmoidf_(vi);
            float gf = sigmoidf_(vf);
            float gg = tanhf(vg);
            float go = sigmoidf_(vo);
            float c  = gf * creg + gi * gg;
            creg = c;
            float h = go * tanhf(c);
            int j = j0 + cj;
            g_out[((size_t)cb * S_ + t) * HID_ + j] = (t < len) ? h : 0.f;
            __nv_bfloat16 hi = __float2bfloat16(h);
            float lo = h - __bfloat162float(hi);
            g_hh[(t + 1) & 1][cb * HID_ + j] = hi;
            g_hl[(t + 1) & 1][cb * HID_ + j] = __float2bfloat16(lo);
        }
        __threadfence();
        __syncthreads();
        if (tid == 0) atomicAdd(&g_bar, 1u);
    }
}

// ---------------- softmax (reference zero-mask semantics) -----------------
__global__ void softmax_mask()
{
    int w    = threadIdx.x >> 5;
    int lane = threadIdx.x & 31;
    int row  = blockIdx.x * 4 + w;
    int t    = row & (S_ - 1);
    float* sc = g_sc + (size_t)row * S_;

    float v[4];
#pragma unroll
    for (int u = 0; u < 4; u++) {
        int s = lane + u * 32;
        float x = sc[s];
        v[u] = (s < t) ? x : 0.f;
    }
    float m = fmaxf(fmaxf(v[0], v[1]), fmaxf(v[2], v[3]));
#pragma unroll
    for (int off = 16; off > 0; off >>= 1)
        m = fmaxf(m, __shfl_xor_sync(0xffffffffu, m, off));
    float e[4], sum = 0.f;
#pragma unroll
    for (int u = 0; u < 4; u++) { e[u] = expf(v[u] - m); sum += e[u]; }
#pragma unroll
    for (int off = 16; off > 0; off >>= 1)
        sum += __shfl_xor_sync(0xffffffffu, sum, off);
    float inv = 1.f / sum;
#pragma unroll
    for (int u = 0; u < 4; u++) {
        int s = lane + u * 32;
        sc[s] = (s < t) ? e[u] * inv : 0.f;
    }
}

// ---------------- attn = (alpha*mask) @ out -------------------------------
__global__ __launch_bounds__(256)
void attn_mm()
{
    int b  = blockIdx.y;
    int t0 = blockIdx.x * 16;
    __shared__ float al[16][128];
    int tid = threadIdx.x;
    for (int i = tid; i < 16 * 128; i += 256)
        al[i >> 7][i & 127] = g_sc[((size_t)b * S_ + t0 + (i >> 7)) * S_ + (i & 127)];
    __syncthreads();

    int d0 = tid * 2;
    float2 acc[16];
#pragma unroll
    for (int t = 0; t < 16; t++) acc[t] = make_float2(0.f, 0.f);

    for (int s = 0; s < 128; s++) {
        float2 o = *(const float2*)&g_out[((size_t)b * S_ + s) * HID_ + d0];
#pragma unroll
        for (int t = 0; t < 16; t++) {
            float a = al[t][s];
            acc[t].x += a * o.x;
            acc[t].y += a * o.y;
        }
    }
#pragma unroll
    for (int t = 0; t < 16; t++)
        *(float2*)&g_attn[((size_t)b * S_ + t0 + t) * HID_ + d0] = acc[t];
}

// ---------------- launch --------------------------------------------------
extern "C" void kernel_launch(void* const* d_in, const int* in_sizes, int n_in,
                              void* d_out, int out_size)
{
    const float* x      = (const float*)d_in[0];
    const int*   y      = (const int*)  d_in[1];
    const int*   len    = (const int*)  d_in[2];
    const float* fc1_w  = (const float*)d_in[3];
    const float* fc1_b  = (const float*)d_in[4];
    const float* bn_g   = (const float*)d_in[5];
    const float* bn_b   = (const float*)d_in[6];
    const float* emb    = (const float*)d_in[7];
    const float* w_ih   = (const float*)d_in[8];
    const float* w_hh   = (const float*)d_in[9];
    const float* b_ih   = (const float*)d_in[10];
    const float* b_hh   = (const float*)d_in[11];
    const float* fc2_w  = (const float*)d_in[12];
    const float* fc2_b  = (const float*)d_in[13];
    float* out = (float*)d_out;

    float *p_seq, *p_xw, *p_out, *p_sc, *p_attn;
    __nv_bfloat16 *p_abf, *p_wbf, *p_sbf, *p_wihbf;
    cudaGetSymbolAddress((void**)&p_seq,   g_seq);
    cudaGetSymbolAddress((void**)&p_xw,    g_xw);
    cudaGetSymbolAddress((void**)&p_out,   g_out);
    cudaGetSymbolAddress((void**)&p_sc,    g_sc);
    cudaGetSymbolAddress((void**)&p_attn,  g_attn);
    cudaGetSymbolAddress((void**)&p_abf,   g_abf);
    cudaGetSymbolAddress((void**)&p_wbf,   g_wbf);
    cudaGetSymbolAddress((void**)&p_sbf,   g_sbf);
    cudaGetSymbolAddress((void**)&p_wihbf, g_wihbf);

    const int LSTM_SMEM = (16 + 16 + 64 + 64) * LW_STRIDE * 2 + 64 * 17 * 4;
    cudaFuncSetAttribute(lstm_mma, cudaFuncAttributeMaxDynamicSharedMemorySize, LSTM_SMEM);

    // fc1 + bn + embedding
    fc1_part<<<dim3(8, 8), 256>>>(x, fc1_w);
    fc1_reduce<<<64, 512>>>(fc1_b);
    bn_k<<<EMB_, 64>>>(bn_g, bn_b);
    embed_k<<<(B_ * T_ * (EMB_ / 4) + 255) / 256, 256>>>(y, emb);

    // xW = seq @ w_ih^T + b_ih + b_hh  (bf16 3-term warp-MMA)
    cvt_split<<<(MS_ * 512 + 255) / 256, 256>>>(p_seq, p_sbf, MS_, MS_, 1);
    cvt_split<<<(2048 * 512 + 255) / 256, 256>>>(w_ih, p_wihbf, 2048, 2048, 0);
    bf16_gemm_mma<<<dim3(16, 64), 256>>>(p_sbf, p_wihbf, b_ih, b_hh,
                                         p_xw, 2048, 2048);

    // recurrent LSTM (persistent, bf16 mma)
    zero_k<<<128, 256>>>();
    lstm_mma<<<128, 256, LSTM_SMEM>>>(w_hh, len);

    // attention
    sgemm_nt<<<dim3(1, 1, B_), 256>>>(p_out, p_out, p_sc,
                                      S_, S_, HID_, S_ * HID_, S_ * HID_, S_ * S_);
    softmax_mask<<<MS_ / 4, 128>>>();
    attn_mm<<<dim3(8, B_), 256>>>();

    // predictions = attn @ fc2_w^T + fc2_b  (bf16 3-term warp-MMA)
    cvt_split<<<(MS_ * 512 + 255) / 256, 256>>>(p_attn, p_abf, MS_, MS_, 1);
    cvt_split<<<(VPAD_ * 512 + 255) / 256, 256>>>(fc2_w, p_wbf, VOCAB_, VPAD_, 0);
    bf16_gemm_mma<<<dim3(79, 64), 256>>>(p_abf, p_wbf, fc2_b, nullptr,
                                         out, VOCAB_, VOCAB_);
}